// round 2
// baseline (speedup 1.0000x reference)
#include <cuda_runtime.h>
#include <cuda_bf16.h>

#define N_NODES 100000
#define N_EDGES 1200000
#define FDIM 64

// ---------------- scratch (device globals; no allocation allowed) -------------
__device__ int   g_is64;
__device__ int   g_src[N_EDGES];
__device__ int   g_dst[N_EDGES];
__device__ float g_norm[N_EDGES];
__device__ int   g_deg[N_NODES];
__device__ float g_dinv[N_NODES];
__device__ float g_tx1[N_NODES * FDIM];
__device__ float g_p2 [N_NODES * FDIM];
__device__ float g_hA [N_NODES * FDIM];
__device__ float g_hB [N_NODES * FDIM];

// ---------------- dtype detection: int64 edge_index has zero high words -------
__global__ void detect_kernel(const int* __restrict__ ei32) {
    if (threadIdx.x != 0 || blockIdx.x != 0) return;
    int odd_zero = 1;
    for (int i = 0; i < 512; i++) {
        if (ei32[2 * i + 1] != 0) { odd_zero = 0; break; }
    }
    g_is64 = odd_zero;
}

// ---------------- small utility kernels --------------------------------------
__global__ void zero_f4_kernel(float4* p, int n4) {
    int i = blockIdx.x * blockDim.x + threadIdx.x;
    if (i < n4) p[i] = make_float4(0.f, 0.f, 0.f, 0.f);
}

__global__ void zero_deg_kernel() {
    int i = blockIdx.x * blockDim.x + threadIdx.x;
    if (i < N_NODES) g_deg[i] = 0;
}

// convert edge index (either dtype) -> int32, count out-degree of src
__global__ void convert_count_kernel(const void* __restrict__ ei) {
    int e = blockIdx.x * blockDim.x + threadIdx.x;
    if (e >= N_EDGES) return;
    int s, d;
    if (g_is64) {
        const long long* p = (const long long*)ei;
        s = (int)p[e];
        d = (int)p[N_EDGES + e];
    } else {
        const int* p = (const int*)ei;
        s = p[e];
        d = p[N_EDGES + e];
    }
    if ((unsigned)s >= N_NODES || (unsigned)d >= N_NODES) { s = 0; d = 0; }
    g_src[e] = s;
    g_dst[e] = d;
    atomicAdd(&g_deg[s], 1);
}

__global__ void dinv_kernel() {
    int i = blockIdx.x * blockDim.x + threadIdx.x;
    if (i >= N_NODES) return;
    int dg = g_deg[i];
    g_dinv[i] = (dg > 0) ? rsqrtf((float)dg) : 0.0f;
}

__global__ void norm_kernel() {
    int e = blockIdx.x * blockDim.x + threadIdx.x;
    if (e >= N_EDGES) return;
    int s = g_src[e], d = g_dst[e];
    float n = -g_dinv[s] * g_dinv[d];
    if (s == 0 && d == 0) {
        // possibly a guarded invalid edge; real (0,0) self-loops contribute
        // norm*h[0] to node 0 — keep them. Guarded edges only arise if dtype
        // detection failed, in which case numbers are wrong anyway.
        n = -g_dinv[0] * g_dinv[0];
    }
    g_norm[e] = n;
}

// ---------------- propagate: out[dst] += norm * in[src] ----------------------
// 16 lanes per edge, float4 per lane, vectorized global reduction (no return).
__global__ __launch_bounds__(256) void prop_kernel(const float* __restrict__ in,
                                                   float* __restrict__ out) {
    long long gt = (long long)blockIdx.x * blockDim.x + threadIdx.x;
    int e    = (int)(gt >> 4);
    int lane = (int)(gt & 15);
    if (e >= N_EDGES) return;
    int   s = g_src[e];
    int   d = g_dst[e];
    float n = g_norm[e];
    const float4 v = *(const float4*)(in + (long long)s * FDIM + lane * 4);
    float4 r;
    r.x = n * v.x; r.y = n * v.y; r.z = n * v.z; r.w = n * v.w;
    float* dp = out + (long long)d * FDIM + lane * 4;
    asm volatile("red.global.add.v4.f32 [%0], {%1,%2,%3,%4};"
                 :: "l"(dp), "f"(r.x), "f"(r.y), "f"(r.z), "f"(r.w)
                 : "memory");
}

// ---------------- fused 3-way GEMM + bias (+skip) + relu ---------------------
// out[r] = inp[r]*W0 + tx1[r]*W1 + (2*p2[r]-inp[r])*W2 + bias (+skip[r]), relu
// block = 256 threads = 64 rows x 4 j-groups (16 outputs each). W in smem.
__global__ __launch_bounds__(256) void gemm_epi_kernel(
    const float* __restrict__ inp, const float* __restrict__ tx1,
    const float* __restrict__ p2,  const float* __restrict__ W,
    const float* __restrict__ bias, const float* __restrict__ skip,
    float* __restrict__ out) {
    __shared__ float sW[3 * FDIM * FDIM];  // 48 KB

    for (int i = threadIdx.x; i < 3 * FDIM * FDIM / 4; i += 256)
        ((float4*)sW)[i] = ((const float4*)W)[i];
    __syncthreads();

    int r = blockIdx.x * 64 + (threadIdx.x >> 2);
    int q = threadIdx.x & 3;
    if (r >= N_NODES) return;
    int jb = q * 16;

    const float* ri = inp + (long long)r * FDIM;
    const float* r1 = tx1 + (long long)r * FDIM;
    const float* r2 = p2  + (long long)r * FDIM;

    float acc[16];
#pragma unroll
    for (int j = 0; j < 16; j++) acc[j] = 0.f;

#pragma unroll 4
    for (int kk = 0; kk < FDIM; kk += 4) {
        float4 a  = *(const float4*)(ri + kk);
        float4 b1 = *(const float4*)(r1 + kk);
        float4 c  = *(const float4*)(r2 + kk);
        float av[4] = {a.x, a.y, a.z, a.w};
        float bv[4] = {b1.x, b1.y, b1.z, b1.w};
        float tv[4] = {2.f * c.x - a.x, 2.f * c.y - a.y,
                       2.f * c.z - a.z, 2.f * c.w - a.w};
#pragma unroll
        for (int u = 0; u < 4; u++) {
            int k = kk + u;
            const float* w0 = sW + k * FDIM + jb;
            const float* w1 = sW + 4096 + k * FDIM + jb;
            const float* w2 = sW + 8192 + k * FDIM + jb;
#pragma unroll
            for (int j = 0; j < 16; j++)
                acc[j] += av[u] * w0[j] + bv[u] * w1[j] + tv[u] * w2[j];
        }
    }

#pragma unroll
    for (int j = 0; j < 16; j++) {
        float v = acc[j] + bias[jb + j];
        if (skip) v += skip[(long long)r * FDIM + jb + j];
        v = fmaxf(v, 0.f);
        out[(long long)r * FDIM + jb + j] = v;
    }
}

// ---------------- launch orchestration ---------------------------------------
static inline int cdiv(long long a, long long b) { return (int)((a + b - 1) / b); }

extern "C" void kernel_launch(void* const* d_in, const int* in_sizes, int n_in,
                              void* d_out, int out_size) {
    const float* x  = (const float*)d_in[0];      // [100000, 64]
    const void*  ei = d_in[1];                    // [2, 1200000] int32 or int64
    const float* W  = (const float*)d_in[2];      // [3, 3, 64, 64]
    const float* b  = (const float*)d_in[3];      // [3, 64]
    float*       out = (float*)d_out;             // [100000, 64]

    float *tx1, *p2, *hA, *hB;
    cudaGetSymbolAddress((void**)&tx1, g_tx1);
    cudaGetSymbolAddress((void**)&p2,  g_p2);
    cudaGetSymbolAddress((void**)&hA,  g_hA);
    cudaGetSymbolAddress((void**)&hB,  g_hB);

    const int feat4 = N_NODES * FDIM / 4;

    // ---- graph prep (recomputed every replay; deterministic) ----
    detect_kernel<<<1, 32>>>((const int*)ei);
    zero_deg_kernel<<<cdiv(N_NODES, 256), 256>>>();
    convert_count_kernel<<<cdiv(N_EDGES, 256), 256>>>(ei);
    dinv_kernel<<<cdiv(N_NODES, 256), 256>>>();
    norm_kernel<<<cdiv(N_EDGES, 256), 256>>>();

    const int prop_grid = cdiv((long long)N_EDGES * 16, 256);
    const int gemm_grid = cdiv(N_NODES, 64);

    // ---- layer 0: inp = x, out -> hA, no skip ----
    zero_f4_kernel<<<cdiv(feat4, 256), 256>>>((float4*)tx1, feat4);
    prop_kernel<<<prop_grid, 256>>>(x, tx1);
    zero_f4_kernel<<<cdiv(feat4, 256), 256>>>((float4*)p2, feat4);
    prop_kernel<<<prop_grid, 256>>>(tx1, p2);
    gemm_epi_kernel<<<gemm_grid, 256>>>(x, tx1, p2, W, b, nullptr, hA);

    // ---- layer 1: inp = hA, out -> hB, skip = hA ----
    zero_f4_kernel<<<cdiv(feat4, 256), 256>>>((float4*)tx1, feat4);
    prop_kernel<<<prop_grid, 256>>>(hA, tx1);
    zero_f4_kernel<<<cdiv(feat4, 256), 256>>>((float4*)p2, feat4);
    prop_kernel<<<prop_grid, 256>>>(tx1, p2);
    gemm_epi_kernel<<<gemm_grid, 256>>>(hA, tx1, p2, W + 3 * FDIM * FDIM,
                                        b + FDIM, hA, hB);

    // ---- layer 2: inp = hB, out -> d_out, skip = hB ----
    zero_f4_kernel<<<cdiv(feat4, 256), 256>>>((float4*)tx1, feat4);
    prop_kernel<<<prop_grid, 256>>>(hB, tx1);
    zero_f4_kernel<<<cdiv(feat4, 256), 256>>>((float4*)p2, feat4);
    prop_kernel<<<prop_grid, 256>>>(tx1, p2);
    gemm_epi_kernel<<<gemm_grid, 256>>>(hB, tx1, p2, W + 6 * FDIM * FDIM,
                                        b + 2 * FDIM, hB, out);
}

// round 3
// speedup vs baseline: 1.2433x; 1.2433x over previous
#include <cuda_runtime.h>
#include <cuda_bf16.h>

#define N_NODES 100000
#define N_EDGES 1200000
#define FDIM 64
#define NB_SCAN ((N_NODES + 1023) / 1024)   // 98

// ---------------- scratch (device globals; no allocation allowed) -------------
__device__ int   g_is64;
__device__ int   g_src[N_EDGES];
__device__ int   g_dst[N_EDGES];
__device__ int   g_degs[N_NODES];          // out-degree of src (for norm)
__device__ int   g_degd[N_NODES];          // in-degree of dst (for CSR)
__device__ float g_dinv[N_NODES];
__device__ int   g_rowptr[N_NODES + 1];
__device__ int   g_cursor[N_NODES];
__device__ int   g_bsum[NB_SCAN];
__device__ int2  g_edge[N_EDGES];          // (src, norm-as-int) sorted by dst
__device__ float g_tx1[N_NODES * FDIM];
__device__ float g_p2 [N_NODES * FDIM];
__device__ float g_hA [N_NODES * FDIM];
__device__ float g_hB [N_NODES * FDIM];
__device__ float g_Wp [3][3 * FDIM * FDIM];  // transformed weights per layer

// ---------------- dtype detection: int64 edge_index has zero high words -------
__global__ void detect_kernel(const int* __restrict__ ei32) {
    if (threadIdx.x != 0 || blockIdx.x != 0) return;
    int odd_zero = 1;
    for (int i = 0; i < 512; i++)
        if (ei32[2 * i + 1] != 0) { odd_zero = 0; break; }
    g_is64 = odd_zero;
}

__global__ void zero_deg_kernel() {
    int i = blockIdx.x * blockDim.x + threadIdx.x;
    if (i < N_NODES) { g_degs[i] = 0; g_degd[i] = 0; }
}

// convert edge index -> int32, count src out-degree and dst in-degree
__global__ void convert_count_kernel(const void* __restrict__ ei) {
    int e = blockIdx.x * blockDim.x + threadIdx.x;
    if (e >= N_EDGES) return;
    int s, d;
    if (g_is64) {
        const long long* p = (const long long*)ei;
        s = (int)p[e]; d = (int)p[N_EDGES + e];
    } else {
        const int* p = (const int*)ei;
        s = p[e]; d = p[N_EDGES + e];
    }
    if ((unsigned)s >= N_NODES || (unsigned)d >= N_NODES) { s = 0; d = 0; }
    g_src[e] = s;
    g_dst[e] = d;
    atomicAdd(&g_degs[s], 1);
    atomicAdd(&g_degd[d], 1);
}

__global__ void dinv_kernel() {
    int i = blockIdx.x * blockDim.x + threadIdx.x;
    if (i >= N_NODES) return;
    int dg = g_degs[i];
    g_dinv[i] = (dg > 0) ? rsqrtf((float)dg) : 0.0f;
}

// ---- CSR build: exclusive scan of g_degd into g_rowptr (3 kernels) ----------
__global__ __launch_bounds__(1024) void scan1_kernel() {
    __shared__ int s[1024];
    int tid = threadIdx.x;
    int i = blockIdx.x * 1024 + tid;
    int v = (i < N_NODES) ? g_degd[i] : 0;
    s[tid] = v;
    __syncthreads();
    for (int off = 1; off < 1024; off <<= 1) {
        int t = (tid >= off) ? s[tid - off] : 0;
        __syncthreads();
        s[tid] += t;
        __syncthreads();
    }
    int incl = s[tid];
    if (i < N_NODES) g_rowptr[i] = incl - v;       // exclusive within block
    if (tid == 1023) g_bsum[blockIdx.x] = incl;    // block total
}

__global__ void scan2_kernel() {
    if (threadIdx.x != 0 || blockIdx.x != 0) return;
    int run = 0;
    for (int i = 0; i < NB_SCAN; i++) {
        int v = g_bsum[i];
        g_bsum[i] = run;
        run += v;
    }
    g_rowptr[N_NODES] = N_EDGES;
}

__global__ void scan3_kernel() {
    int i = blockIdx.x * blockDim.x + threadIdx.x;
    if (i >= N_NODES) return;
    int v = g_rowptr[i] + g_bsum[i >> 10];
    g_rowptr[i] = v;
    g_cursor[i] = v;
}

// scatter edges into CSR slots; compute norm at fill time
__global__ void fill_kernel() {
    int e = blockIdx.x * blockDim.x + threadIdx.x;
    if (e >= N_EDGES) return;
    int s = g_src[e], d = g_dst[e];
    int pos = atomicAdd(&g_cursor[d], 1);
    float nv = -g_dinv[s] * g_dinv[d];
    g_edge[pos] = make_int2(s, __float_as_int(nv));
}

// ---- weight pre-transform: W0' = W0 - W2, W1' = W1, W2' = 2*W2 --------------
__global__ void wprep_kernel(const float* __restrict__ W) {
    int i = blockIdx.x * blockDim.x + threadIdx.x;
    if (i >= 3 * 3 * 4096) return;
    int layer = i / 12288, rem = i % 12288;
    int t = rem / 4096, idx = rem % 4096;
    const float* Wl = W + layer * 12288;
    float v;
    if (t == 0)      v = Wl[idx] - Wl[2 * 4096 + idx];
    else if (t == 1) v = Wl[4096 + idx];
    else             v = 2.0f * Wl[2 * 4096 + idx];
    g_Wp[layer][t * 4096 + idx] = v;
}

// ---------------- pull-mode propagate: out[n] = sum_e norm_e * in[src_e] -----
// 16 lanes per node (float4 each). Edge list contiguous per node (CSR).
__global__ __launch_bounds__(256) void pull_kernel(const float* __restrict__ in,
                                                   float* __restrict__ out) {
    int t = blockIdx.x * 256 + threadIdx.x;
    int node = t >> 4;
    int lane = t & 15;
    if (node >= N_NODES) return;
    int e   = g_rowptr[node];
    int end = g_rowptr[node + 1];
    float4 acc = make_float4(0.f, 0.f, 0.f, 0.f);
    for (; e < end; e++) {
        int2 ed = __ldg(&g_edge[e]);                 // broadcast across 16 lanes
        float nv = __int_as_float(ed.y);
        const float4 v = *(const float4*)(in + ed.x * FDIM + lane * 4);
        acc.x = fmaf(nv, v.x, acc.x);
        acc.y = fmaf(nv, v.y, acc.y);
        acc.z = fmaf(nv, v.z, acc.z);
        acc.w = fmaf(nv, v.w, acc.w);
    }
    *(float4*)(out + node * FDIM + lane * 4) = acc;
}

// ---------------- fused 3-way GEMM (FFMA2) + bias (+skip) + relu -------------
// out[r] = t0[r]*W0' + t1[r]*W1' + p2[r]*W2' + bias (+skip), relu
// 256 threads = 64 rows x 4 j-groups of 16. Packed f32x2 accumulators.
__device__ __forceinline__ void fma2(unsigned long long& acc,
                                     unsigned long long w,
                                     unsigned long long a) {
    asm("fma.rn.f32x2 %0, %1, %2, %0;" : "+l"(acc) : "l"(w), "l"(a));
}

__global__ __launch_bounds__(256) void gemm_epi_kernel(
    const float* __restrict__ t0, const float* __restrict__ t1,
    const float* __restrict__ p2, const float* __restrict__ Wp,
    const float* __restrict__ bias, const float* __restrict__ skip,
    float* __restrict__ out) {
    __shared__ float sW[3 * FDIM * FDIM];  // 48 KB

    for (int i = threadIdx.x; i < 3 * FDIM * FDIM / 4; i += 256)
        ((float4*)sW)[i] = ((const float4*)Wp)[i];
    __syncthreads();

    int r = blockIdx.x * 64 + (threadIdx.x >> 2);
    int q = threadIdx.x & 3;
    if (r >= N_NODES) return;
    int jb = q * 16;

    const float* r0 = t0 + r * FDIM;
    const float* r1 = t1 + r * FDIM;
    const float* r2 = p2 + r * FDIM;

    unsigned long long acc[8];
#pragma unroll
    for (int i = 0; i < 8; i++) acc[i] = 0ULL;  // bits of (0.f, 0.f)

#pragma unroll 4
    for (int kk = 0; kk < FDIM; kk += 4) {
        float4 a = *(const float4*)(r0 + kk);
        float4 b = *(const float4*)(r1 + kk);
        float4 c = *(const float4*)(r2 + kk);
        float av[4] = {a.x, a.y, a.z, a.w};
        float bv[4] = {b.x, b.y, b.z, b.w};
        float cv[4] = {c.x, c.y, c.z, c.w};
#pragma unroll
        for (int u = 0; u < 4; u++) {
            int k = kk + u;
            unsigned long long a2, b2, c2;
            asm("mov.b64 %0, {%1, %1};" : "=l"(a2) : "f"(av[u]));
            asm("mov.b64 %0, {%1, %1};" : "=l"(b2) : "f"(bv[u]));
            asm("mov.b64 %0, {%1, %1};" : "=l"(c2) : "f"(cv[u]));
            const ulonglong2* w0 = (const ulonglong2*)(sW + k * FDIM + jb);
            const ulonglong2* w1 = (const ulonglong2*)(sW + 4096 + k * FDIM + jb);
            const ulonglong2* w2 = (const ulonglong2*)(sW + 8192 + k * FDIM + jb);
#pragma unroll
            for (int p = 0; p < 4; p++) {
                ulonglong2 wa = w0[p];
                fma2(acc[2 * p], wa.x, a2);
                fma2(acc[2 * p + 1], wa.y, a2);
            }
#pragma unroll
            for (int p = 0; p < 4; p++) {
                ulonglong2 wb = w1[p];
                fma2(acc[2 * p], wb.x, b2);
                fma2(acc[2 * p + 1], wb.y, b2);
            }
#pragma unroll
            for (int p = 0; p < 4; p++) {
                ulonglong2 wc = w2[p];
                fma2(acc[2 * p], wc.x, c2);
                fma2(acc[2 * p + 1], wc.y, c2);
            }
        }
    }

    float o[16];
#pragma unroll
    for (int i = 0; i < 8; i++) {
        float f0, f1;
        asm("mov.b64 {%0, %1}, %2;" : "=f"(f0), "=f"(f1) : "l"(acc[i]));
        o[2 * i]     = f0;
        o[2 * i + 1] = f1;
    }
#pragma unroll
    for (int j = 0; j < 16; j++) {
        float v = o[j] + bias[jb + j];
        if (skip) v += skip[r * FDIM + jb + j];
        o[j] = fmaxf(v, 0.f);
    }
#pragma unroll
    for (int p = 0; p < 4; p++)
        *(float4*)(out + r * FDIM + jb + 4 * p) =
            make_float4(o[4 * p], o[4 * p + 1], o[4 * p + 2], o[4 * p + 3]);
}

// ---------------- launch orchestration ---------------------------------------
static inline int cdiv(long long a, long long b) { return (int)((a + b - 1) / b); }

extern "C" void kernel_launch(void* const* d_in, const int* in_sizes, int n_in,
                              void* d_out, int out_size) {
    const float* x  = (const float*)d_in[0];      // [100000, 64]
    const void*  ei = d_in[1];                    // [2, 1200000] int32 or int64
    const float* W  = (const float*)d_in[2];      // [3, 3, 64, 64]
    const float* b  = (const float*)d_in[3];      // [3, 64]
    float*       out = (float*)d_out;             // [100000, 64]

    float *tx1, *p2, *hA, *hB, *Wp0;
    cudaGetSymbolAddress((void**)&tx1, g_tx1);
    cudaGetSymbolAddress((void**)&p2,  g_p2);
    cudaGetSymbolAddress((void**)&hA,  g_hA);
    cudaGetSymbolAddress((void**)&hB,  g_hB);
    cudaGetSymbolAddress((void**)&Wp0, g_Wp);

    // ---- graph prep: dtype detect, degrees, dinv, CSR (counting sort) ----
    detect_kernel<<<1, 32>>>((const int*)ei);
    zero_deg_kernel<<<cdiv(N_NODES, 256), 256>>>();
    convert_count_kernel<<<cdiv(N_EDGES, 256), 256>>>(ei);
    dinv_kernel<<<cdiv(N_NODES, 256), 256>>>();
    scan1_kernel<<<NB_SCAN, 1024>>>();
    scan2_kernel<<<1, 32>>>();
    scan3_kernel<<<cdiv(N_NODES, 256), 256>>>();
    fill_kernel<<<cdiv(N_EDGES, 256), 256>>>();
    wprep_kernel<<<cdiv(3 * 3 * 4096, 256), 256>>>(W);

    const int pull_grid = cdiv((long long)N_NODES * 16, 256);
    const int gemm_grid = cdiv(N_NODES, 64);

    // ---- layer 0: inp = x -> hA (no skip) ----
    pull_kernel<<<pull_grid, 256>>>(x, tx1);
    pull_kernel<<<pull_grid, 256>>>(tx1, p2);
    gemm_epi_kernel<<<gemm_grid, 256>>>(x, tx1, p2, Wp0, b, nullptr, hA);

    // ---- layer 1: inp = hA -> hB (skip = hA) ----
    pull_kernel<<<pull_grid, 256>>>(hA, tx1);
    pull_kernel<<<pull_grid, 256>>>(tx1, p2);
    gemm_epi_kernel<<<gemm_grid, 256>>>(hA, tx1, p2, Wp0 + 3 * 4096,
                                        b + FDIM, hA, hB);

    // ---- layer 2: inp = hB -> d_out (skip = hB) ----
    pull_kernel<<<pull_grid, 256>>>(hB, tx1);
    pull_kernel<<<pull_grid, 256>>>(tx1, p2);
    gemm_epi_kernel<<<gemm_grid, 256>>>(hB, tx1, p2, Wp0 + 6 * 4096,
                                        b + 2 * FDIM, hB, out);
}

// round 4
// speedup vs baseline: 1.7919x; 1.4412x over previous
#include <cuda_runtime.h>
#include <cuda_bf16.h>

#define N_NODES 100000
#define N_EDGES 1200000
#define FDIM 64
#define NB_SCAN ((N_NODES + 1023) / 1024)   // 98

// ---------------- scratch (device globals; no allocation allowed) -------------
__device__ int   g_is64;
__device__ int   g_degs[N_NODES];          // out-degree of src (for norm)
__device__ int   g_degd[N_NODES];          // in-degree of dst (for CSR)
__device__ float g_dinv[N_NODES];
__device__ int   g_rowptr[N_NODES + 1];
__device__ int   g_cursor[N_NODES];
__device__ int   g_bsum[NB_SCAN];
__device__ int2  g_edge[N_EDGES];          // (src, norm-as-int) grouped by dst
__device__ float g_tx1[N_NODES * FDIM];
__device__ float g_p2 [N_NODES * FDIM];
__device__ float g_hA [N_NODES * FDIM];
__device__ float g_hB [N_NODES * FDIM];
__device__ float g_Wp [3][3 * FDIM * FDIM];  // transformed weights per layer

// ---------------- dtype detection: int64 edge_index has zero high words -------
__global__ void detect_kernel(const int* __restrict__ ei32) {
    if (threadIdx.x != 0 || blockIdx.x != 0) return;
    int odd_zero = 1;
    for (int i = 0; i < 512; i++)
        if (ei32[2 * i + 1] != 0) { odd_zero = 0; break; }
    g_is64 = odd_zero;
}

__global__ void zero_deg_kernel() {
    int i = blockIdx.x * blockDim.x + threadIdx.x;
    if (i < N_NODES) { g_degs[i] = 0; g_degd[i] = 0; }
}

__device__ __forceinline__ void load_edge(const void* ei, int e, int& s, int& d) {
    if (g_is64) {
        const long long* p = (const long long*)ei;
        s = (int)p[e]; d = (int)p[N_EDGES + e];
    } else {
        const int* p = (const int*)ei;
        s = p[e]; d = p[N_EDGES + e];
    }
    if ((unsigned)s >= N_NODES || (unsigned)d >= N_NODES) { s = 0; d = 0; }
}

// count src out-degree and dst in-degree
__global__ void count_kernel(const void* __restrict__ ei) {
    int e = blockIdx.x * blockDim.x + threadIdx.x;
    if (e >= N_EDGES) return;
    int s, d;
    load_edge(ei, e, s, d);
    atomicAdd(&g_degs[s], 1);
    atomicAdd(&g_degd[d], 1);
}

__global__ void dinv_kernel() {
    int i = blockIdx.x * blockDim.x + threadIdx.x;
    if (i >= N_NODES) return;
    int dg = g_degs[i];
    g_dinv[i] = (dg > 0) ? rsqrtf((float)dg) : 0.0f;
}

// ---- CSR build: exclusive scan of g_degd into g_rowptr ----------------------
__global__ __launch_bounds__(1024) void scan1_kernel() {
    __shared__ int s[1024];
    int tid = threadIdx.x;
    int i = blockIdx.x * 1024 + tid;
    int v = (i < N_NODES) ? g_degd[i] : 0;
    s[tid] = v;
    __syncthreads();
    for (int off = 1; off < 1024; off <<= 1) {
        int t = (tid >= off) ? s[tid - off] : 0;
        __syncthreads();
        s[tid] += t;
        __syncthreads();
    }
    int incl = s[tid];
    if (i < N_NODES) g_rowptr[i] = incl - v;
    if (tid == 1023) g_bsum[blockIdx.x] = incl;
}

__global__ void scan2_kernel() {
    if (threadIdx.x != 0 || blockIdx.x != 0) return;
    int run = 0;
    for (int i = 0; i < NB_SCAN; i++) {
        int v = g_bsum[i];
        g_bsum[i] = run;
        run += v;
    }
    g_rowptr[N_NODES] = N_EDGES;
}

__global__ void scan3_kernel() {
    int i = blockIdx.x * blockDim.x + threadIdx.x;
    if (i >= N_NODES) return;
    int v = g_rowptr[i] + g_bsum[i >> 10];
    g_rowptr[i] = v;
    g_cursor[i] = v;
}

// scatter edges into CSR slots; compute norm at fill time
__global__ void fill_kernel(const void* __restrict__ ei) {
    int e = blockIdx.x * blockDim.x + threadIdx.x;
    if (e >= N_EDGES) return;
    int s, d;
    load_edge(ei, e, s, d);
    int pos = atomicAdd(&g_cursor[d], 1);
    float nv = -g_dinv[s] * g_dinv[d];
    g_edge[pos] = make_int2(s, __float_as_int(nv));
}

// ---- weight pre-transform: W0' = W0 - W2, W1' = W1, W2' = 2*W2 --------------
__global__ void wprep_kernel(const float* __restrict__ W) {
    int i = blockIdx.x * blockDim.x + threadIdx.x;
    if (i >= 3 * 3 * 4096) return;
    int layer = i / 12288, rem = i % 12288;
    int t = rem / 4096, idx = rem % 4096;
    const float* Wl = W + layer * 12288;
    float v;
    if (t == 0)      v = Wl[idx] - Wl[2 * 4096 + idx];
    else if (t == 1) v = Wl[4096 + idx];
    else             v = 2.0f * Wl[2 * 4096 + idx];
    g_Wp[layer][t * 4096 + idx] = v;
}

// ---------------- pull-mode propagate (unrolled x4 for MLP) ------------------
// 16 lanes per node, float4 per lane. out[n] = sum_e norm_e * in[src_e].
__global__ __launch_bounds__(256) void pull_kernel(const float* __restrict__ in,
                                                   float* __restrict__ out) {
    int t = blockIdx.x * 256 + threadIdx.x;
    int node = t >> 4;
    int lane = t & 15;
    if (node >= N_NODES) return;
    int e   = __ldg(&g_rowptr[node]);
    int end = __ldg(&g_rowptr[node + 1]);
    float4 acc = make_float4(0.f, 0.f, 0.f, 0.f);

    for (; e + 4 <= end; e += 4) {
        int2 e0 = __ldg(&g_edge[e]);
        int2 e1 = __ldg(&g_edge[e + 1]);
        int2 e2 = __ldg(&g_edge[e + 2]);
        int2 e3 = __ldg(&g_edge[e + 3]);
        float4 v0 = __ldg((const float4*)(in + e0.x * FDIM + lane * 4));
        float4 v1 = __ldg((const float4*)(in + e1.x * FDIM + lane * 4));
        float4 v2 = __ldg((const float4*)(in + e2.x * FDIM + lane * 4));
        float4 v3 = __ldg((const float4*)(in + e3.x * FDIM + lane * 4));
        float n0 = __int_as_float(e0.y), n1 = __int_as_float(e1.y);
        float n2 = __int_as_float(e2.y), n3 = __int_as_float(e3.y);
        acc.x = fmaf(n0, v0.x, acc.x); acc.y = fmaf(n0, v0.y, acc.y);
        acc.z = fmaf(n0, v0.z, acc.z); acc.w = fmaf(n0, v0.w, acc.w);
        acc.x = fmaf(n1, v1.x, acc.x); acc.y = fmaf(n1, v1.y, acc.y);
        acc.z = fmaf(n1, v1.z, acc.z); acc.w = fmaf(n1, v1.w, acc.w);
        acc.x = fmaf(n2, v2.x, acc.x); acc.y = fmaf(n2, v2.y, acc.y);
        acc.z = fmaf(n2, v2.z, acc.z); acc.w = fmaf(n2, v2.w, acc.w);
        acc.x = fmaf(n3, v3.x, acc.x); acc.y = fmaf(n3, v3.y, acc.y);
        acc.z = fmaf(n3, v3.z, acc.z); acc.w = fmaf(n3, v3.w, acc.w);
    }
    for (; e < end; e++) {
        int2 ed = __ldg(&g_edge[e]);
        float nv = __int_as_float(ed.y);
        float4 v = __ldg((const float4*)(in + ed.x * FDIM + lane * 4));
        acc.x = fmaf(nv, v.x, acc.x); acc.y = fmaf(nv, v.y, acc.y);
        acc.z = fmaf(nv, v.z, acc.z); acc.w = fmaf(nv, v.w, acc.w);
    }
    *(float4*)(out + node * FDIM + lane * 4) = acc;
}

// ---------------- fused 3-way GEMM (FFMA2, 2 rows/thread) --------------------
// out[r] = t0[r]*W0' + t1[r]*W1' + p2[r]*W2' + bias (+skip), relu
// 256 threads = 64 row-slots x 4 j-groups; each thread does 2 rows (+64 apart).
__device__ __forceinline__ void fma2(unsigned long long& acc,
                                     unsigned long long w,
                                     unsigned long long a) {
    asm("fma.rn.f32x2 %0, %1, %2, %0;" : "+l"(acc) : "l"(w), "l"(a));
}
__device__ __forceinline__ unsigned long long splat2(float f) {
    unsigned long long r;
    asm("mov.b64 %0, {%1, %1};" : "=l"(r) : "f"(f));
    return r;
}

__global__ __launch_bounds__(256) void gemm_epi_kernel(
    const float* __restrict__ t0, const float* __restrict__ t1,
    const float* __restrict__ p2, const float* __restrict__ Wp,
    const float* __restrict__ bias, const float* __restrict__ skip,
    float* __restrict__ out) {
    __shared__ float sW[3 * FDIM * FDIM];  // 48 KB

    for (int i = threadIdx.x; i < 3 * FDIM * FDIM / 4; i += 256)
        ((float4*)sW)[i] = ((const float4*)Wp)[i];
    __syncthreads();

    int base = blockIdx.x * 128;
    int rg = threadIdx.x >> 2;          // 0..63
    int q  = threadIdx.x & 3;
    int jb = q * 16;
    int rA = base + rg;
    int rB = base + rg + 64;
    bool okA = rA < N_NODES, okB = rB < N_NODES;
    if (!okA) return;                   // rows are dense; okA false => okB false

    const float* a0 = t0 + rA * FDIM;  const float* a1 = t1 + rA * FDIM;
    const float* a2p = p2 + rA * FDIM;
    const float* b0 = t0 + rB * FDIM;  const float* b1 = t1 + rB * FDIM;
    const float* b2p = p2 + rB * FDIM;

    unsigned long long accA[8], accB[8];
#pragma unroll
    for (int i = 0; i < 8; i++) { accA[i] = 0ULL; accB[i] = 0ULL; }

#pragma unroll 2
    for (int kk = 0; kk < FDIM; kk += 4) {
        float4 xa0 = __ldg((const float4*)(a0 + kk));
        float4 xa1 = __ldg((const float4*)(a1 + kk));
        float4 xa2 = __ldg((const float4*)(a2p + kk));
        float4 xb0, xb1, xb2;
        if (okB) {
            xb0 = __ldg((const float4*)(b0 + kk));
            xb1 = __ldg((const float4*)(b1 + kk));
            xb2 = __ldg((const float4*)(b2p + kk));
        } else {
            xb0 = xb1 = xb2 = make_float4(0.f, 0.f, 0.f, 0.f);
        }
        float fa0[4] = {xa0.x, xa0.y, xa0.z, xa0.w};
        float fa1[4] = {xa1.x, xa1.y, xa1.z, xa1.w};
        float fa2[4] = {xa2.x, xa2.y, xa2.z, xa2.w};
        float fb0[4] = {xb0.x, xb0.y, xb0.z, xb0.w};
        float fb1[4] = {xb1.x, xb1.y, xb1.z, xb1.w};
        float fb2[4] = {xb2.x, xb2.y, xb2.z, xb2.w};
#pragma unroll
        for (int u = 0; u < 4; u++) {
            int k = kk + u;
            const ulonglong2* w0 = (const ulonglong2*)(sW + k * FDIM + jb);
            const ulonglong2* w1 = (const ulonglong2*)(sW + 4096 + k * FDIM + jb);
            const ulonglong2* w2 = (const ulonglong2*)(sW + 8192 + k * FDIM + jb);
            {
                unsigned long long sA = splat2(fa0[u]), sB = splat2(fb0[u]);
#pragma unroll
                for (int p = 0; p < 4; p++) {
                    ulonglong2 w = w0[p];
                    fma2(accA[2 * p], w.x, sA); fma2(accA[2 * p + 1], w.y, sA);
                    fma2(accB[2 * p], w.x, sB); fma2(accB[2 * p + 1], w.y, sB);
                }
            }
            {
                unsigned long long sA = splat2(fa1[u]), sB = splat2(fb1[u]);
#pragma unroll
                for (int p = 0; p < 4; p++) {
                    ulonglong2 w = w1[p];
                    fma2(accA[2 * p], w.x, sA); fma2(accA[2 * p + 1], w.y, sA);
                    fma2(accB[2 * p], w.x, sB); fma2(accB[2 * p + 1], w.y, sB);
                }
            }
            {
                unsigned long long sA = splat2(fa2[u]), sB = splat2(fb2[u]);
#pragma unroll
                for (int p = 0; p < 4; p++) {
                    ulonglong2 w = w2[p];
                    fma2(accA[2 * p], w.x, sA); fma2(accA[2 * p + 1], w.y, sA);
                    fma2(accB[2 * p], w.x, sB); fma2(accB[2 * p + 1], w.y, sB);
                }
            }
        }
    }

    float bia[16];
#pragma unroll
    for (int j = 0; j < 16; j++) bia[j] = bias[jb + j];

    // epilogue row A
    {
        float o[16];
#pragma unroll
        for (int i = 0; i < 8; i++) {
            float f0, f1;
            asm("mov.b64 {%0, %1}, %2;" : "=f"(f0), "=f"(f1) : "l"(accA[i]));
            o[2 * i] = f0; o[2 * i + 1] = f1;
        }
#pragma unroll
        for (int j = 0; j < 16; j++) {
            float v = o[j] + bia[j];
            if (skip) v += skip[rA * FDIM + jb + j];
            o[j] = fmaxf(v, 0.f);
        }
#pragma unroll
        for (int p = 0; p < 4; p++)
            *(float4*)(out + rA * FDIM + jb + 4 * p) =
                make_float4(o[4*p], o[4*p+1], o[4*p+2], o[4*p+3]);
    }
    // epilogue row B
    if (okB) {
        float o[16];
#pragma unroll
        for (int i = 0; i < 8; i++) {
            float f0, f1;
            asm("mov.b64 {%0, %1}, %2;" : "=f"(f0), "=f"(f1) : "l"(accB[i]));
            o[2 * i] = f0; o[2 * i + 1] = f1;
        }
#pragma unroll
        for (int j = 0; j < 16; j++) {
            float v = o[j] + bia[j];
            if (skip) v += skip[rB * FDIM + jb + j];
            o[j] = fmaxf(v, 0.f);
        }
#pragma unroll
        for (int p = 0; p < 4; p++)
            *(float4*)(out + rB * FDIM + jb + 4 * p) =
                make_float4(o[4*p], o[4*p+1], o[4*p+2], o[4*p+3]);
    }
}

// ---------------- launch orchestration ---------------------------------------
static inline int cdiv(long long a, long long b) { return (int)((a + b - 1) / b); }

extern "C" void kernel_launch(void* const* d_in, const int* in_sizes, int n_in,
                              void* d_out, int out_size) {
    const float* x  = (const float*)d_in[0];      // [100000, 64]
    const void*  ei = d_in[1];                    // [2, 1200000] int32 or int64
    const float* W  = (const float*)d_in[2];      // [3, 3, 64, 64]
    const float* b  = (const float*)d_in[3];      // [3, 64]
    float*       out = (float*)d_out;             // [100000, 64]

    float *tx1, *p2, *hA, *hB, *Wp0;
    cudaGetSymbolAddress((void**)&tx1, g_tx1);
    cudaGetSymbolAddress((void**)&p2,  g_p2);
    cudaGetSymbolAddress((void**)&hA,  g_hA);
    cudaGetSymbolAddress((void**)&hB,  g_hB);
    cudaGetSymbolAddress((void**)&Wp0, g_Wp);

    // ---- graph prep: dtype detect, degrees, dinv, CSR (counting sort) ----
    detect_kernel<<<1, 32>>>((const int*)ei);
    zero_deg_kernel<<<cdiv(N_NODES, 256), 256>>>();
    count_kernel<<<cdiv(N_EDGES, 256), 256>>>(ei);
    dinv_kernel<<<cdiv(N_NODES, 256), 256>>>();
    scan1_kernel<<<NB_SCAN, 1024>>>();
    scan2_kernel<<<1, 32>>>();
    scan3_kernel<<<cdiv(N_NODES, 256), 256>>>();
    fill_kernel<<<cdiv(N_EDGES, 256), 256>>>(ei);
    wprep_kernel<<<cdiv(3 * 3 * 4096, 256), 256>>>(W);

    const int pull_grid = cdiv((long long)N_NODES * 16, 256);
    const int gemm_grid = cdiv(N_NODES, 128);

    // ---- layer 0: inp = x -> hA (no skip) ----
    pull_kernel<<<pull_grid, 256>>>(x, tx1);
    pull_kernel<<<pull_grid, 256>>>(tx1, p2);
    gemm_epi_kernel<<<gemm_grid, 256>>>(x, tx1, p2, Wp0, b, nullptr, hA);

    // ---- layer 1: inp = hA -> hB (skip = hA) ----
    pull_kernel<<<pull_grid, 256>>>(hA, tx1);
    pull_kernel<<<pull_grid, 256>>>(tx1, p2);
    gemm_epi_kernel<<<gemm_grid, 256>>>(hA, tx1, p2, Wp0 + 3 * 4096,
                                        b + FDIM, hA, hB);

    // ---- layer 2: inp = hB -> d_out (skip = hB) ----
    pull_kernel<<<pull_grid, 256>>>(hB, tx1);
    pull_kernel<<<pull_grid, 256>>>(tx1, p2);
    gemm_epi_kernel<<<gemm_grid, 256>>>(hB, tx1, p2, Wp0 + 6 * 4096,
                                        b + 2 * FDIM, hB, out);
}